// round 3
// baseline (speedup 1.0000x reference)
#include <cuda_runtime.h>
#include <cstdint>

#define B        4
#define T        1024
#define HALF     256      // VALUE_DIM / 2
#define C        256
#define NLAB     64
#define VDIM     512

#define NBLK     256      // (l, ch): 64 labels x 4 d-chunks of 64
#define NTHR     256
#define CAP      96       // token-list capacity per (b, label); E[n]=16, 12+ sigma margin

// Scratch output accumulator (B*C floats). Invariant: zero at entry to every
// launch (static zero-init + consume-and-clear by the last block).
__device__ float        g_out[B * C];
__device__ unsigned int g_done;   // block-completion counter, self-resetting

__global__ void __launch_bounds__(NTHR)
vb_fused_kernel(const int*   __restrict__ indices,
                const float* __restrict__ scores,
                const float* __restrict__ W,
                const int*   __restrict__ label,
                const int*   __restrict__ index_p,
                const float* __restrict__ weight,
                float*       __restrict__ out) {
    __shared__ int   s_cnt[B];
    __shared__ int   s_tok[B][CAP];
    __shared__ float s_sc [B][CAP];
    __shared__ float sA[B][64];
    __shared__ int   s_last;

    const int tid = threadIdx.x;
    const int l   = blockIdx.x >> 2;   // label
    const int ch  = blockIdx.x & 3;    // d-chunk of 64
    const int off = (*index_p == 1) ? HALF : 0;
    const int dbase = off + ch * 64;

    if (tid < B) s_cnt[tid] = 0;
    __syncthreads();

    // --- Phase A: scan labels, build per-b token lists ----------------------
    #pragma unroll
    for (int k = 0; k < (B * T) / NTHR; k++) {
        const int i = k * NTHR + tid;
        if (label[i] == l) {
            const int b = i >> 10;                 // i = b*T + t
            const int p = atomicAdd(&s_cnt[b], 1);
            if (p < CAP) {
                s_tok[b][p] = indices[i];
                s_sc [b][p] = scores[i];
            }
        }
    }
    __syncthreads();

    // --- Phase B: gather-accumulate A[b, l, dbase+dd] in registers ----------
    // Thread layout: b = tid>>6, dd = tid&63. Each group of 64 threads loads
    // 256B contiguous per token (coalesced), 8-way software pipelined.
    {
        const int b  = tid >> 6;
        const int dd = tid & 63;
        const int n  = min(s_cnt[b], CAP);
        float acc = 0.0f;
        int j = 0;
        for (; j + 8 <= n; j += 8) {
            float w[8], s[8];
            #pragma unroll
            for (int u = 0; u < 8; u++) {
                const int   idx = s_tok[b][j + u];
                s[u] = s_sc[b][j + u];
                w[u] = __ldg(weight + (size_t)idx * VDIM + dbase + dd);
            }
            #pragma unroll
            for (int u = 0; u < 8; u++) acc += s[u] * w[u];
        }
        for (; j < n; j++) {
            const int idx = s_tok[b][j];
            acc += s_sc[b][j] * __ldg(weight + (size_t)idx * VDIM + dbase + dd);
        }
        sA[b][dd] = acc;
    }
    __syncthreads();

    // --- Phase C: contract  partial[b,c] = sum_dd sA[b][dd] * W[l, dbase+dd, c]
    // Thread = output column c.
    {
        const float* Wb = W + ((size_t)l * VDIM + dbase) * C + tid;
        float a0 = 0.f, a1 = 0.f, a2 = 0.f, a3 = 0.f;
        #pragma unroll
        for (int d = 0; d < 64; d++) {
            const float w = __ldg(Wb + (size_t)d * C);   // coalesced across c
            a0 += sA[0][d] * w;
            a1 += sA[1][d] * w;
            a2 += sA[2][d] * w;
            a3 += sA[3][d] * w;
        }
        atomicAdd(&g_out[0 * C + tid], a0);
        atomicAdd(&g_out[1 * C + tid], a1);
        atomicAdd(&g_out[2 * C + tid], a2);
        atomicAdd(&g_out[3 * C + tid], a3);
    }

    // --- Tail: last finished block publishes g_out -> out, then clears ------
    __threadfence();          // make this thread's atomics globally visible
    __syncthreads();          // all threads in block past their fence
    if (tid == 0) {
        const unsigned r = atomicAdd(&g_done, 1u);
        s_last = (r == (unsigned)(NBLK - 1)) ? 1 : 0;
    }
    __syncthreads();

    if (s_last) {
        #pragma unroll
        for (int k = 0; k < (B * C) / NTHR; k++) {
            const int i = k * NTHR + tid;
            out[i]   = __ldcg(&g_out[i]);   // L2 read: sees all atomics
            g_out[i] = 0.0f;                // restore invariant for next launch
        }
        if (tid == 0) atomicExch(&g_done, 0u);
    }
}

// ---------------------------------------------------------------------------
// Inputs (metadata order):
//   0: indices (B,T) int32     1: scores (B,T) f32
//   2: W (64,512,256) f32      3: label (B,T) int32
//   4: index scalar int32      5: weight (262144,512) f32
// Output: (B, C) f32 = 1024 floats
// ---------------------------------------------------------------------------
extern "C" void kernel_launch(void* const* d_in, const int* in_sizes, int n_in,
                              void* d_out, int out_size) {
    const int*   indices = (const int*)  d_in[0];
    const float* scores  = (const float*)d_in[1];
    const float* W       = (const float*)d_in[2];
    const int*   label   = (const int*)  d_in[3];
    const int*   index_p = (const int*)  d_in[4];
    const float* weight  = (const float*)d_in[5];
    float*       out     = (float*)d_out;

    vb_fused_kernel<<<NBLK, NTHR>>>(indices, scores, W, label, index_p,
                                    weight, out);
}

// round 4
// speedup vs baseline: 1.0151x; 1.0151x over previous
#include <cuda_runtime.h>
#include <cstdint>

#define B        4
#define T        1024
#define HALF     256      // VALUE_DIM / 2
#define C        256
#define NLAB     64
#define VDIM     512

#define CBLK     256      // contract grid: (l=64) x (ch=4)

// Scratch A[b][l][d] (65536 floats). Invariant: zero at entry to every launch
// (static zero-init; contract kernel consume-and-clears its exclusive slice).
__device__ float g_A[B * NLAB * HALF];

// Scratch output accumulator + completion counter (self-resetting).
__device__ float        g_out[B * C];
__device__ unsigned int g_done;

// ---------------------------------------------------------------------------
// Kernel 1: scatter-accumulate
//   A[b, label[b,t], d] += score[b,t] * weight[idx[b,t], off + d]
// One warp per token; two float4 loads + two float4 vector atomics per lane.
// ---------------------------------------------------------------------------
__global__ void __launch_bounds__(256)
vb_scatter_kernel(const int*   __restrict__ indices,
                  const float* __restrict__ scores,
                  const int*   __restrict__ label,
                  const int*   __restrict__ index_p,
                  const float* __restrict__ weight) {
    const int gwarp = (blockIdx.x * blockDim.x + threadIdx.x) >> 5;  // token
    const int lane  = threadIdx.x & 31;

    const int   idx = indices[gwarp];     // warp-uniform broadcast
    const float sc  = scores[gwarp];
    const int   lab = label[gwarp];
    const int   off = (*index_p == 1) ? HALF : 0;
    const int   b   = gwarp >> 10;        // gwarp = b*T + t

    const float4* wrow = reinterpret_cast<const float4*>(
        weight + (size_t)idx * VDIM + off);
    float4 v0 = __ldg(wrow + lane);
    float4 v1 = __ldg(wrow + lane + 32);
    v0.x *= sc; v0.y *= sc; v0.z *= sc; v0.w *= sc;
    v1.x *= sc; v1.y *= sc; v1.z *= sc; v1.w *= sc;

    float4* dst = reinterpret_cast<float4*>(
        g_A + (size_t)(b * NLAB + lab) * HALF);
    atomicAdd(dst + lane,      v0);
    atomicAdd(dst + lane + 32, v1);
}

// ---------------------------------------------------------------------------
// Kernel 2: contraction + consume-and-clear + last-block publish
//   partial[b,c] = sum_{d in chunk} A[b,l,d] * W[l, off+d, c]  -> g_out atomics
//   last block: out = g_out; g_out = 0; g_done = 0
// Block (l, ch): l = bid>>2, ch = bid&3 (d-chunk of 64). Thread = column c.
// ---------------------------------------------------------------------------
__global__ void __launch_bounds__(256)
vb_contract_kernel(const float* __restrict__ W,
                   const int*   __restrict__ index_p,
                   float*       __restrict__ out) {
    __shared__ float sA[B][64];
    __shared__ int   s_last;

    const int tid = threadIdx.x;
    const int l   = blockIdx.x >> 2;
    const int ch  = blockIdx.x & 3;
    const int off = (*index_p == 1) ? HALF : 0;

    // Stage A slice and clear it (exclusive ownership -> race-free).
    {
        const int b  = tid >> 6;
        const int dd = tid & 63;
        float* ap = &g_A[(size_t)(b * NLAB + l) * HALF + ch * 64 + dd];
        sA[b][dd] = __ldcg(ap);
        *ap = 0.0f;                      // restore zero invariant for next replay
    }
    __syncthreads();

    const float* Wb = W + ((size_t)l * VDIM + off + ch * 64) * C + tid;

    float a0 = 0.f, a1 = 0.f, a2 = 0.f, a3 = 0.f;
#pragma unroll
    for (int d = 0; d < 64; d++) {
        const float w = __ldg(Wb + (size_t)d * C);   // coalesced across c
        a0 += sA[0][d] * w;
        a1 += sA[1][d] * w;
        a2 += sA[2][d] * w;
        a3 += sA[3][d] * w;
    }

    atomicAdd(&g_out[0 * C + tid], a0);
    atomicAdd(&g_out[1 * C + tid], a1);
    atomicAdd(&g_out[2 * C + tid], a2);
    atomicAdd(&g_out[3 * C + tid], a3);

    // Tail: last finished block publishes g_out -> out and clears scratch.
    __threadfence();
    __syncthreads();
    if (tid == 0) {
        const unsigned r = atomicAdd(&g_done, 1u);
        s_last = (r == (unsigned)(CBLK - 1)) ? 1 : 0;
    }
    __syncthreads();

    if (s_last) {
#pragma unroll
        for (int k = 0; k < (B * C) / 256; k++) {
            const int i = k * 256 + tid;
            out[i]   = __ldcg(&g_out[i]);   // sees all blocks' atomics
            g_out[i] = 0.0f;
        }
        if (tid == 0) atomicExch(&g_done, 0u);
    }
}

// ---------------------------------------------------------------------------
// Inputs (metadata order):
//   0: indices (B,T) int32     1: scores (B,T) f32
//   2: W (64,512,256) f32      3: label (B,T) int32
//   4: index scalar int32      5: weight (262144,512) f32
// Output: (B, C) f32 = 1024 floats
// ---------------------------------------------------------------------------
extern "C" void kernel_launch(void* const* d_in, const int* in_sizes, int n_in,
                              void* d_out, int out_size) {
    const int*   indices = (const int*)  d_in[0];
    const float* scores  = (const float*)d_in[1];
    const float* W       = (const float*)d_in[2];
    const int*   label   = (const int*)  d_in[3];
    const int*   index_p = (const int*)  d_in[4];
    const float* weight  = (const float*)d_in[5];
    float*       out     = (float*)d_out;

    // 1) scatter: B*T = 4096 warps -> 512 blocks x 256 threads
    vb_scatter_kernel<<<512, 256>>>(indices, scores, label, index_p, weight);

    // 2) contraction: 64 labels x 4 d-chunks
    vb_contract_kernel<<<CBLK, 256>>>(W, index_p, out);
}